// round 16
// baseline (speedup 1.0000x reference)
#include <cuda_runtime.h>

#define B    100
#define DIN  2048
#define DH   1024
#define DOUT 1000

__device__ __align__(16) float d_hacc[B * DH];   // gemm1 + b1 acc (pre-scaled 1/DIN)
__device__ int d_cnt[4];       // last-reader counters: d_hacc 256-col k-slices

#define G1_BLOCKS 256              // gemm1: 16 ntiles x 16 ksplits (kc=128)
#define OZ_BLOCKS 98               // out-zero: 98*256 float4 = 25088 >= 25000
#define R1_BLOCKS 1600             // b1: 100 batches x 16 chunks (128 rows)
#define MA_GRID   (G1_BLOCKS + OZ_BLOCKS + R1_BLOCKS)

#define G2_SPLITS 4                // gemm2 k-splits (kc=256)
#define G2_BLOCKS (16 * G2_SPLITS) // 64: only 64 non-streaming first-wave slots
#define R2_BLOCKS 1600             // b2: 100 batches x 16 chunks (64 rows)
#define MB_GRID   (G2_BLOCKS + R2_BLOCKS)

// One L2 reduction op per 16 bytes (sm_90+): 4x fewer atomic ops than four
// scalar atomicAdds. Address must be 16B-aligned (all call sites are).
__device__ __forceinline__ void red_add_v4(float* p, float a, float b,
                                           float c, float d) {
    asm volatile("red.global.add.v4.f32 [%0], {%1, %2, %3, %4};"
                 :: "l"(__cvta_generic_to_global(p)),
                    "f"(a), "f"(b), "f"(c), "f"(d)
                 : "memory");
}

// ---------------------------------------------------------------------------
// SIMT GEMM tile: all 100 M-rows x 64 N-cols, K range [k0, k0+kc).
// 256 threads: thread owns 7 m x 4 n. Accumulates scale*r via v4 reductions.
// relu_in: max(v,0) on A load. zslice >= 0: last-reader re-zero of d_hacc
// cols [zslice*256, +256) — 16 readers (one per n-tile); the 16th restores
// the zero invariant for the next graph replay.
__device__ __forceinline__ void gemm_block(const float* __restrict__ A,
                                           const float* __restrict__ Wm,
                                           float* __restrict__ acc,
                                           int K, int N, int ldacc,
                                           int k0, int kc, int n0,
                                           float scale, bool relu_in,
                                           int zslice) {
    __shared__ __align__(16) float xs[112][33]; // pad 33: strips hit distinct banks
    __shared__ __align__(16) float ws[32][64];
    __shared__ int do_zero;

    const int tid = threadIdx.x;
    const int nl4 = tid & 15;        // 16 lanes * 4 cols = 64
    const int m0  = (tid >> 4) * 7;  // 16 strips * 7 = 112 >= 100

    float r[7][4];
#pragma unroll
    for (int i = 0; i < 7; ++i)
#pragma unroll
        for (int j = 0; j < 4; ++j) r[i][j] = 0.f;

    for (int kb = k0; kb < k0 + kc; kb += 32) {
        for (int idx = tid; idx < 112 * 32; idx += 256) {
            int m = idx >> 5, kk = idx & 31;
            float v = (m < B) ? A[(long long)m * K + kb + kk] : 0.f;
            if (relu_in) v = fmaxf(v, 0.f);
            xs[m][kk] = v;
        }
        for (int idx = tid; idx < 32 * 64; idx += 256) {
            int kk = idx >> 6, nn = idx & 63;
            int nc = n0 + nn;
            ws[kk][nn] = (nc < N) ? Wm[(long long)(kb + kk) * N + nc] : 0.f;
        }
        __syncthreads();
#pragma unroll
        for (int kk = 0; kk < 32; ++kk) {
            float4 wv = *(const float4*)&ws[kk][nl4 * 4];
#pragma unroll
            for (int mi = 0; mi < 7; ++mi) {
                float xv = xs[m0 + mi][kk];
                r[mi][0] += xv * wv.x; r[mi][1] += xv * wv.y;
                r[mi][2] += xv * wv.z; r[mi][3] += xv * wv.w;
            }
        }
        __syncthreads();
    }

#pragma unroll
    for (int mi = 0; mi < 7; ++mi) {
        int m = m0 + mi;
        int n = n0 + nl4 * 4;
        // n and N are multiples of 4, so each quad is all-in or all-out.
        if (m < B && n + 4 <= N)
            red_add_v4(&acc[(long long)m * ldacc + n],
                       r[mi][0] * scale, r[mi][1] * scale,
                       r[mi][2] * scale, r[mi][3] * scale);
    }

    if (zslice >= 0) {
        if (tid == 0) {
            int old = atomicAdd(&d_cnt[zslice], 1);
            do_zero = (old == 15);
            if (old == 15) d_cnt[zslice] = 0;   // self-reset for next replay
        }
        __syncthreads();
        if (do_zero) {
            int c0 = zslice * 256;
            for (int idx = tid; idx < B * 256; idx += 256)
                d_hacc[(idx >> 8) * DH + c0 + (idx & 255)] = 0.f;
        }
    }
}

// ---------------------------------------------------------------------------
// Column-sum of `rows` rows of a [rows_total x width] slab into acc row b,
// scaled. Coalesced float4 loads; unroll-16 front-batches 16 in-flight
// float4 loads per thread regardless of `rows`; v4 reduction epilogue.
__device__ __forceinline__ void reduce_block(const float* __restrict__ src,
                                             float* __restrict__ acc,
                                             int b, int chunk, int rows,
                                             int rows_total, int width,
                                             float scale) {
    const int wq = width >> 2;
    const int j4 = threadIdx.x;
    if (j4 >= wq) return;
    const long long base = (long long)b * rows_total * width +
                           (long long)chunk * rows * width + j4 * 4;
    const float4* p = (const float4*)(src + base);
    float4 s = make_float4(0.f, 0.f, 0.f, 0.f);
#pragma unroll 16
    for (int i = 0; i < rows; ++i) {
        float4 v = p[(long long)i * wq];
        s.x += v.x; s.y += v.y; s.z += v.z; s.w += v.w;
    }
    red_add_v4(acc + (long long)b * width + j4 * 4,
               s.x * scale, s.y * scale, s.z * scale, s.w * scale);
}

// ---------------------------------------------------------------------------
// megaA: gemm1 (256) + out-zero (98) + b1 (1600, 128-row) -> d_hacc / out.
__global__ void megaA_kernel(const float* __restrict__ x,
                             const float* __restrict__ W1,
                             const float* __restrict__ b1,
                             float* __restrict__ out) {
    int bid = blockIdx.x;
    if (bid < G1_BLOCKS) {
        int nt = bid & 15, ks = bid >> 4;
        gemm_block(x, W1, d_hacc, DIN, DH, DH, ks * 128, 128, nt * 64,
                   1.0f / DIN, false, -1);
    } else if (bid < G1_BLOCKS + OZ_BLOCKS) {
        int i4 = (bid - G1_BLOCKS) * 256 + threadIdx.x;
        if (i4 < (B * DOUT) / 4)
            ((float4*)out)[i4] = make_float4(0.f, 0.f, 0.f, 0.f);
    } else {
        int r = bid - (G1_BLOCKS + OZ_BLOCKS);
        reduce_block(b1, d_hacc, r >> 4, r & 15, 128, DIN, DH, 1.0f / DIN);
    }
}

// ---------------------------------------------------------------------------
// megaB: gemm2 (64 blocks: 16 nt x 4 ks, kc=256; relu on A-load; d_hacc
// slice re-zero) -> out ; ALL of b2 as 1600 blocks of 64-row chunks -> out.
// Only 64 of 592 first-wave slots are non-streaming; small units give
// fine-grained backfill and a short straggler tail. out was zeroed in megaA.
__global__ void megaB_kernel(const float* __restrict__ W2,
                             const float* __restrict__ b2,
                             float* __restrict__ out) {
    int bid = blockIdx.x;
    if (bid < G2_BLOCKS) {
        int nt = bid & 15, ks = bid >> 4;
        gemm_block(d_hacc, W2, out, DH, DOUT, DOUT, ks * 256, 256, nt * 64,
                   1.0f / DH, true, ks);
    } else {
        int r = bid - G2_BLOCKS;
        reduce_block(b2, out, r >> 4, r & 15, 64, DH, DOUT, 1.0f / DH);
    }
}

// ---------------------------------------------------------------------------
extern "C" void kernel_launch(void* const* d_in, const int* in_sizes, int n_in,
                              void* d_out, int out_size) {
    const float* x  = (const float*)d_in[0];
    const float* W1 = (const float*)d_in[1];
    const float* b1 = (const float*)d_in[2];
    const float* W2 = (const float*)d_in[3];
    const float* b2 = (const float*)d_in[4];
    float* out = (float*)d_out;

    megaA_kernel<<<MA_GRID, 256>>>(x, W1, b1, out);
    megaB_kernel<<<MB_GRID, 256>>>(W2, b2, out);
}

// round 17
// speedup vs baseline: 1.0979x; 1.0979x over previous
#include <cuda_runtime.h>

#define B    100
#define DIN  2048
#define DH   1024
#define DOUT 1000

__device__ __align__(16) float d_hacc[B * DH];   // gemm1 + b1 acc (pre-scaled 1/DIN)
__device__ int d_cnt[8];       // last-reader counters: d_hacc 128-col k-slices

#define G1_BLOCKS 256              // gemm1: 16 ntiles x 16 ksplits (kc=128)
#define OZ_BLOCKS 98               // out-zero: 98*256 float4 = 25088 >= 25000
#define R1_BLOCKS 1600             // b1: 100 batches x 16 chunks (128 rows)
#define MA_GRID   (G1_BLOCKS + OZ_BLOCKS + R1_BLOCKS)

#define G2_SPLITS 8                // gemm2 k-splits (kc=128)
#define G2_BLOCKS (16 * G2_SPLITS) // 128 non-streaming first-wave slots
#define R2_BLOCKS 800              // b2: 100 batches x 8 chunks (128 rows)
#define MB_GRID   (G2_BLOCKS + R2_BLOCKS)

// One L2 reduction op per 16 bytes (sm_90+): 4x fewer atomic ops than four
// scalar atomicAdds. Address must be 16B-aligned (all call sites are).
__device__ __forceinline__ void red_add_v4(float* p, float a, float b,
                                           float c, float d) {
    asm volatile("red.global.add.v4.f32 [%0], {%1, %2, %3, %4};"
                 :: "l"(__cvta_generic_to_global(p)),
                    "f"(a), "f"(b), "f"(c), "f"(d)
                 : "memory");
}

// ---------------------------------------------------------------------------
// SIMT GEMM tile: all 100 M-rows x 64 N-cols, K range [k0, k0+kc).
// 256 threads: thread owns 7 m x 4 n. Accumulates scale*r via v4 reductions.
// relu_in: max(v,0) on A load. zslice >= 0: last-reader re-zero of d_hacc
// cols [zslice*128, +128) — 16 readers (one per n-tile); the 16th restores
// the zero invariant for the next graph replay.
__device__ __forceinline__ void gemm_block(const float* __restrict__ A,
                                           const float* __restrict__ Wm,
                                           float* __restrict__ acc,
                                           int K, int N, int ldacc,
                                           int k0, int kc, int n0,
                                           float scale, bool relu_in,
                                           int zslice) {
    __shared__ __align__(16) float xs[112][33]; // pad 33: strips hit distinct banks
    __shared__ __align__(16) float ws[32][64];
    __shared__ int do_zero;

    const int tid = threadIdx.x;
    const int nl4 = tid & 15;        // 16 lanes * 4 cols = 64
    const int m0  = (tid >> 4) * 7;  // 16 strips * 7 = 112 >= 100

    float r[7][4];
#pragma unroll
    for (int i = 0; i < 7; ++i)
#pragma unroll
        for (int j = 0; j < 4; ++j) r[i][j] = 0.f;

    for (int kb = k0; kb < k0 + kc; kb += 32) {
        for (int idx = tid; idx < 112 * 32; idx += 256) {
            int m = idx >> 5, kk = idx & 31;
            float v = (m < B) ? A[(long long)m * K + kb + kk] : 0.f;
            if (relu_in) v = fmaxf(v, 0.f);
            xs[m][kk] = v;
        }
        for (int idx = tid; idx < 32 * 64; idx += 256) {
            int kk = idx >> 6, nn = idx & 63;
            int nc = n0 + nn;
            ws[kk][nn] = (nc < N) ? Wm[(long long)(kb + kk) * N + nc] : 0.f;
        }
        __syncthreads();
#pragma unroll
        for (int kk = 0; kk < 32; ++kk) {
            float4 wv = *(const float4*)&ws[kk][nl4 * 4];
#pragma unroll
            for (int mi = 0; mi < 7; ++mi) {
                float xv = xs[m0 + mi][kk];
                r[mi][0] += xv * wv.x; r[mi][1] += xv * wv.y;
                r[mi][2] += xv * wv.z; r[mi][3] += xv * wv.w;
            }
        }
        __syncthreads();
    }

#pragma unroll
    for (int mi = 0; mi < 7; ++mi) {
        int m = m0 + mi;
        int n = n0 + nl4 * 4;
        // n and N are multiples of 4, so each quad is all-in or all-out.
        if (m < B && n + 4 <= N)
            red_add_v4(&acc[(long long)m * ldacc + n],
                       r[mi][0] * scale, r[mi][1] * scale,
                       r[mi][2] * scale, r[mi][3] * scale);
    }

    if (zslice >= 0) {
        if (tid == 0) {
            int old = atomicAdd(&d_cnt[zslice], 1);
            do_zero = (old == 15);
            if (old == 15) d_cnt[zslice] = 0;   // self-reset for next replay
        }
        __syncthreads();
        if (do_zero) {
            int c0 = zslice * 128;
            for (int idx = tid; idx < B * 128; idx += 256)
                d_hacc[(idx >> 7) * DH + c0 + (idx & 127)] = 0.f;
        }
    }
}

// ---------------------------------------------------------------------------
// Column-sum of `rows` rows of a [rows_total x width] slab into acc row b,
// scaled. Coalesced float4 loads; 128-row bursts (validated optimum — do not
// shrink: 64-row chunks measured 20-25% lower BW in R6/R14); v4 reduction.
__device__ __forceinline__ void reduce_block(const float* __restrict__ src,
                                             float* __restrict__ acc,
                                             int b, int chunk, int rows,
                                             int rows_total, int width,
                                             float scale) {
    const int wq = width >> 2;
    const int j4 = threadIdx.x;
    if (j4 >= wq) return;
    const long long base = (long long)b * rows_total * width +
                           (long long)chunk * rows * width + j4 * 4;
    const float4* p = (const float4*)(src + base);
    float4 s = make_float4(0.f, 0.f, 0.f, 0.f);
#pragma unroll 16
    for (int i = 0; i < rows; ++i) {
        float4 v = p[(long long)i * wq];
        s.x += v.x; s.y += v.y; s.z += v.z; s.w += v.w;
    }
    red_add_v4(acc + (long long)b * width + j4 * 4,
               s.x * scale, s.y * scale, s.z * scale, s.w * scale);
}

// ---------------------------------------------------------------------------
// megaA: gemm1 (256) + out-zero (98) + b1 (1600, 128-row) -> d_hacc / out.
__global__ void megaA_kernel(const float* __restrict__ x,
                             const float* __restrict__ W1,
                             const float* __restrict__ b1,
                             float* __restrict__ out) {
    int bid = blockIdx.x;
    if (bid < G1_BLOCKS) {
        int nt = bid & 15, ks = bid >> 4;
        gemm_block(x, W1, d_hacc, DIN, DH, DH, ks * 128, 128, nt * 64,
                   1.0f / DIN, false, -1);
    } else if (bid < G1_BLOCKS + OZ_BLOCKS) {
        int i4 = (bid - G1_BLOCKS) * 256 + threadIdx.x;
        if (i4 < (B * DOUT) / 4)
            ((float4*)out)[i4] = make_float4(0.f, 0.f, 0.f, 0.f);
    } else {
        int r = bid - (G1_BLOCKS + OZ_BLOCKS);
        reduce_block(b1, d_hacc, r >> 4, r & 15, 128, DIN, DH, 1.0f / DIN);
    }
}

// ---------------------------------------------------------------------------
// megaB: gemm2 (128 blocks: 16 nt x 8 ks, kc=128; relu on A-load; d_hacc
// slice re-zero) -> out ; ALL of b2 (800 blocks, 128-row chunks) -> out.
// 928 blocks: 128 of 592 first-wave slots are non-streaming (vs 256 in the
// kc=64 config); retiring gemm blocks are backfilled by reduce blocks.
// out was zeroed in megaA; every write is a v4 reduction.
__global__ void megaB_kernel(const float* __restrict__ W2,
                             const float* __restrict__ b2,
                             float* __restrict__ out) {
    int bid = blockIdx.x;
    if (bid < G2_BLOCKS) {
        int nt = bid & 15, ks = bid >> 4;
        gemm_block(d_hacc, W2, out, DH, DOUT, DOUT, ks * 128, 128, nt * 64,
                   1.0f / DH, true, ks);
    } else {
        int r = bid - G2_BLOCKS;
        reduce_block(b2, out, r >> 3, r & 7, 128, DH, DOUT, 1.0f / DH);
    }
}

// ---------------------------------------------------------------------------
extern "C" void kernel_launch(void* const* d_in, const int* in_sizes, int n_in,
                              void* d_out, int out_size) {
    const float* x  = (const float*)d_in[0];
    const float* W1 = (const float*)d_in[1];
    const float* b1 = (const float*)d_in[2];
    const float* W2 = (const float*)d_in[3];
    const float* b2 = (const float*)d_in[4];
    float* out = (float*)d_out;

    megaA_kernel<<<MA_GRID, 256>>>(x, W1, b1, out);
    megaB_kernel<<<MB_GRID, 256>>>(W2, b2, out);
}